// round 1
// baseline (speedup 1.0000x reference)
#include <cuda_runtime.h>

#define BB 128
#define SS 512
#define KK 4
#define DD 300
#define CC 20
#define CHUNKS 16
#define SCHUNK (SS / CHUNKS)   // 32
#define TPB 320

// Deterministic scratch: per-(b,chunk) partial feature sums. 128*16*300 floats = 2.4 MB
__device__ float g_partial[BB * CHUNKS * DD];

__global__ void __launch_bounds__(TPB) gather_kernel(
    const int* __restrict__ X, const int* __restrict__ NX, const int* __restrict__ EW,
    const float* __restrict__ node_emb, const float* __restrict__ edge_w,
    const float* __restrict__ node_w)
{
    __shared__ int   sX[SCHUNK];
    __shared__ int   sNX[SCHUNK * KK];
    __shared__ float sNW[SCHUNK];
    __shared__ float sEW[SCHUNK * KK];

    const int b     = blockIdx.y;
    const int chunk = blockIdx.x;
    const int s0    = chunk * SCHUNK;
    const int tid   = threadIdx.x;

    // Phase 1: cooperative prefetch of all indices + scalars for this s-chunk.
    // 32 X/node_w chains + 128 NX loads + 128 EW->edge_w chains, all independent
    // across threads -> one round of DRAM latency instead of 32 serialized.
    if (tid < SCHUNK) {
        int x = X[b * SS + s0 + tid];
        sX[tid]  = x;
        sNW[tid] = node_w[x];
    } else if (tid < SCHUNK + SCHUNK * KK) {
        int i = tid - SCHUNK;
        sNX[i] = NX[(b * SS + s0) * KK + i];
    } else if (tid < SCHUNK + 2 * SCHUNK * KK) {
        int i = tid - SCHUNK - SCHUNK * KK;
        int er = EW[(b * SS + s0) * KK + i];
        sEW[i] = edge_w[er];                 // fully random DRAM gather, high MLP here
    }
    __syncthreads();

    // Phase 2: thread d accumulates feature dim d over the 32 s values.
    // Gathers are coalesced across threads (consecutive d) and hit L2 (node_emb = 12MB).
    const int d = tid;
    if (d < DD) {
        float acc = 0.f;
        #pragma unroll 4
        for (int s = 0; s < SCHUNK; s++) {
            const float nw = sNW[s];
            float m = 0.f;
            #pragma unroll
            for (int k = 0; k < KK; k++) {
                m += sEW[s * KK + k] * __ldg(&node_emb[sNX[s * KK + k] * DD + d]);
            }
            const float r = __ldg(&node_emb[sX[s] * DD + d]);
            acc += (1.f - nw) * m + nw * r;
        }
        g_partial[(b * CHUNKS + chunk) * DD + d] = acc;
    }
}

__global__ void __launch_bounds__(TPB) head_kernel(
    const float* __restrict__ fc_w, const float* __restrict__ fc_b,
    float* __restrict__ out)
{
    __shared__ float sfeat[DD];
    __shared__ float slog[CC];

    const int b   = blockIdx.x;
    const int tid = threadIdx.x;

    // Reduce chunk partials (fixed order -> deterministic)
    if (tid < DD) {
        float f = 0.f;
        #pragma unroll
        for (int c = 0; c < CHUNKS; c++)
            f += g_partial[(b * CHUNKS + c) * DD + tid];
        sfeat[tid] = f;
    }
    __syncthreads();

    // 10 warps x 2 classes each: dot(feats, fc_w[c]) via warp shuffle reduce
    const int warp = tid >> 5, lane = tid & 31;
    #pragma unroll
    for (int cc = 0; cc < 2; cc++) {
        const int c = warp * 2 + cc;
        float p = 0.f;
        for (int dd = lane; dd < DD; dd += 32)
            p += sfeat[dd] * fc_w[c * DD + dd];
        #pragma unroll
        for (int o = 16; o; o >>= 1)
            p += __shfl_down_sync(0xffffffffu, p, o);
        if (lane == 0) slog[c] = p + fc_b[c];
    }
    __syncthreads();

    // relu -> softmax over 20 values: trivial, single thread
    if (tid == 0) {
        float l[CC];
        float mx = 0.f;
        #pragma unroll
        for (int c = 0; c < CC; c++) {
            l[c] = fmaxf(slog[c], 0.f);
            mx = fmaxf(mx, l[c]);
        }
        float sum = 0.f;
        #pragma unroll
        for (int c = 0; c < CC; c++) {
            l[c] = __expf(l[c] - mx);
            sum += l[c];
        }
        const float inv = 1.f / sum;
        #pragma unroll
        for (int c = 0; c < CC; c++)
            out[b * CC + c] = l[c] * inv;
    }
}

extern "C" void kernel_launch(void* const* d_in, const int* in_sizes, int n_in,
                              void* d_out, int out_size)
{
    const int*   X        = (const int*)  d_in[0];
    const int*   NX       = (const int*)  d_in[1];
    const int*   EW       = (const int*)  d_in[2];
    const float* node_emb = (const float*)d_in[3];
    const float* edge_w   = (const float*)d_in[4];
    const float* node_w   = (const float*)d_in[5];
    const float* fc_w     = (const float*)d_in[6];
    const float* fc_b     = (const float*)d_in[7];
    float* out = (float*)d_out;

    dim3 grid1(CHUNKS, BB);
    gather_kernel<<<grid1, TPB>>>(X, NX, EW, node_emb, edge_w, node_w);
    head_kernel<<<BB, TPB>>>(fc_w, fc_b, out);
}